// round 15
// baseline (speedup 1.0000x reference)
#include <cuda_runtime.h>
#include <cuda_fp16.h>
#include <cstdint>
#include <math.h>

// ---------------- problem constants ----------------
#define S_LEN 2048
#define BHN   64          // B*H
#define DQ    64
#define DP    32
#define KC    96          // concatenated K (q|pq)
#define KBP   104         // padded B row stride in halves (208 B)
#define LOG2E 1.4426950408889634f
#define SCALE_Q (0.125f * LOG2E)               // exp2-folded
#define SCALE_P (0.17677669529663687f * LOG2E) // exp2-folded

#define MROWS 32          // rows per tile (full 2048-wide ownership)
#define NSUB  128         // columns per subtile
#define NSUBS 16          // 2048 / 128
#define NTILES ((S_LEN / MROWS) * BHN)   // 4096
#define NCTA  148         // persistent CTAs (1 per SM)
#define SPADB 208         // A/B smem row stride bytes (13*16B, ldmatrix-clean)
#define NSTG  3           // B ring stages per warp
#define WSTAGE 1664       // per-warp per-stage bytes (8 rows * 208) == bulk size
#define WSLAB  (NSTG * WSTAGE)        // 4992 B per warp
#define SROWB  4112       // score smem row stride (4096 + 16 skew: conflict-free)

#define SM_A    0                     // A: 32*208 = 6656
#define SM_RED  6656                  // 32*16 partials (2048) + 32 sums (128) = 2176
#define SM_BAR  8832                  // 16 warps * 3 slots * 8B = 384
#define SM_SC   9216                  // scores: 32 * 4112 = 131584
#define SM_B    140800                // B slabs: 16 * 4992 = 79872
#define SM_TOT  220672

// fp16 scratch. A: [bh][s][96]; B: [bh][s][104] (padded rows -> warp slab is
// 1664 contiguous bytes in gmem, enabling single cp.async.bulk per stage).
__device__ __align__(16) __half g_Ah[(size_t)BHN * S_LEN * KC];
__device__ __align__(16) __half g_Bh[(size_t)BHN * S_LEN * KBP];

__device__ __forceinline__ float clamp5(float x) {
    return fminf(fmaxf(x, -5.0f), 5.0f);
}

__device__ __forceinline__ float ex2f(float x) {     // single MUFU.EX2
    float y;
    asm("ex2.approx.f32 %0, %1;" : "=f"(y) : "f"(x));
    return y;
}

__device__ __forceinline__ uint32_t h2_to_u32(__half2 h) {
    union { __half2 h; uint32_t u; } cv;
    cv.h = h;
    return cv.u;
}

__device__ __forceinline__ uint32_t smem_u32(const void* p) {
    uint32_t a;
    asm("{ .reg .u64 t; cvta.to.shared.u64 t, %1; cvt.u32.u64 %0, t; }" : "=r"(a) : "l"(p));
    return a;
}

// ---- bulk-copy + mbarrier (B stream bypasses the LSU) ----
#define MBARRIER_INIT(mbar, cnt) \
    asm volatile("mbarrier.init.shared.b64 [%0], %1;" :: "r"((uint32_t)(mbar)), "r"((uint32_t)(cnt)) : "memory")
#define MBARRIER_EXPECT_TX(mbar, bytes) \
    asm volatile("mbarrier.arrive.expect_tx.shared.b64 _, [%0], %1;" :: "r"((uint32_t)(mbar)), "r"((uint32_t)(bytes)) : "memory")
__device__ __forceinline__ void bulk_cp(uint32_t dst, const void* src, uint32_t bytes, uint32_t mbar) {
    asm volatile("cp.async.bulk.shared::cta.global.mbarrier::complete_tx::bytes [%0], [%1], %2, [%3];"
                 :: "r"(dst), "l"(src), "r"(bytes), "r"(mbar) : "memory");
}
#define MBARRIER_WAIT_PARITY(mbar, parity) do { \
    uint32_t _m = (uint32_t)(mbar); uint32_t _p = (uint32_t)(parity); uint32_t _d; \
    asm volatile("{\n\t.reg .pred p;\n\t" \
        "mbarrier.try_wait.parity.acquire.cta.shared::cta.b64 p, [%1], %2;\n\t" \
        "selp.b32 %0, 1, 0, p;\n\t}" : "=r"(_d) : "r"(_m), "r"(_p) : "memory"); \
    if (!_d) { \
        asm volatile("{\n\t.reg .pred P1;\n\t" \
            "WL_%=:\n\t" \
            "mbarrier.try_wait.parity.acquire.cta.shared::cta.b64 P1, [%0], %1, 0x989680;\n\t" \
            "@P1 bra.uni WD_%=;\n\t" \
            "bra.uni WL_%=;\n\t" \
            "WD_%=:\n\t}" :: "r"(_m), "r"(_p) : "memory"); \
    } \
} while (0)

__device__ __forceinline__ void ldsm_x4(uint32_t* r, uint32_t addr) {
    asm volatile("ldmatrix.sync.aligned.m8n8.x4.shared.b16 {%0,%1,%2,%3}, [%4];"
                 : "=r"(r[0]), "=r"(r[1]), "=r"(r[2]), "=r"(r[3]) : "r"(addr));
}
__device__ __forceinline__ void mma_fp16(float* d, const uint32_t* a, const uint32_t* b) {
    asm volatile("mma.sync.aligned.m16n8k16.row.col.f32.f16.f16.f32 "
                 "{%0,%1,%2,%3}, {%4,%5,%6,%7}, {%8,%9}, {%0,%1,%2,%3};"
                 : "+f"(d[0]), "+f"(d[1]), "+f"(d[2]), "+f"(d[3])
                 : "r"(a[0]), "r"(a[1]), "r"(a[2]), "r"(a[3]), "r"(b[0]), "r"(b[1]));
}

// ---------------------------------------------------------------------------
// Pass 0: clamp + scale(+log2e on A) + fp16 convert; float4-vectorized.
// B stored with padded 104-half rows.
// ---------------------------------------------------------------------------
__global__ __launch_bounds__(256) void prep_fp16(
    const float* __restrict__ keys, const float* __restrict__ queries,
    const float* __restrict__ pos_key, const float* __restrict__ pos_query)
{
    size_t idx4 = (size_t)blockIdx.x * blockDim.x + threadIdx.x;
    const size_t total4 = (size_t)BHN * S_LEN * (KC / 4);
    if (idx4 >= total4) return;
    size_t row = idx4 / (KC / 4);
    int c0 = (int)(idx4 % (KC / 4)) * 4;
    float4 va, vb;
    if (c0 < DQ) {
        va = *(const float4*)(queries + row * DQ + c0);
        vb = *(const float4*)(keys + row * DQ + c0);
        va.x = clamp5(va.x) * SCALE_Q; va.y = clamp5(va.y) * SCALE_Q;
        va.z = clamp5(va.z) * SCALE_Q; va.w = clamp5(va.w) * SCALE_Q;
    } else {
        va = *(const float4*)(pos_query + row * DP + (c0 - DQ));
        vb = *(const float4*)(pos_key + row * DP + (c0 - DQ));
        va.x = clamp5(va.x) * SCALE_P; va.y = clamp5(va.y) * SCALE_P;
        va.z = clamp5(va.z) * SCALE_P; va.w = clamp5(va.w) * SCALE_P;
    }
    vb.x = clamp5(vb.x); vb.y = clamp5(vb.y);
    vb.z = clamp5(vb.z); vb.w = clamp5(vb.w);
    *(__half2*)(g_Ah + row * KC + c0)      = __floats2half2_rn(va.x, va.y);
    *(__half2*)(g_Ah + row * KC + c0 + 2)  = __floats2half2_rn(va.z, va.w);
    *(__half2*)(g_Bh + row * KBP + c0)     = __floats2half2_rn(vb.x, vb.y);
    *(__half2*)(g_Bh + row * KBP + c0 + 2) = __floats2half2_rn(vb.z, vb.w);
}

// ---------------------------------------------------------------------------
// Pass 1 (fused, persistent): per tile 32x2048 scores -> exp2 (fp16 smem) ->
// fp32 rowsum -> normalized single-pass write. B streamed via warp-private
// 3-stage ring filled by cp.async.bulk (TMA path — zero LDGSTS on the LSU),
// completion tracked by per-(warp,slot) mbarrier parity. Ring runs
// continuously across tile boundaries.
// ---------------------------------------------------------------------------
__global__ __launch_bounds__(512, 1) void fused_attn(float* __restrict__ out)
{
    extern __shared__ __align__(16) char smraw[];
    float* redp = (float*)(smraw + SM_RED);          // [32 rows][16 warps]
    float* rsum = redp + 32 * 16;                    // [32] inverse sums
    const uint32_t sA   = smem_u32(smraw + SM_A);
    const uint32_t sSC  = smem_u32(smraw + SM_SC);
    const uint32_t sBAR = smem_u32(smraw + SM_BAR);

    const int tid = threadIdx.x;
    const int lane = tid & 31, warp = tid >> 5;      // 16 warps
    const int bid = blockIdx.x;

    const uint32_t slab = smem_u32(smraw + SM_B) + warp * WSLAB;
    const uint32_t wbar = sBAR + warp * (NSTG * 8);  // this warp's 3 barriers

    const int r0 = lane >> 2;                       // 0..7
    const int c2 = (lane & 3) * 2;
    const uint32_t bfoff = (lane & 7) * SPADB + (lane >> 3) * 16;
    const uint32_t scbase = sSC + (warp * 8 + c2) * 2;   // + row*SROWB + sub*256

    // --- barrier init (once) ---
    if (tid < 48) MBARRIER_INIT(sBAR + tid * 8, 1);
    __syncthreads();

    // --- first-tile prologue: bulk-issue B stages 0,1; stage A ---
    {
        const int bh0 = bid >> 6;
        const __half* Bg0 = g_Bh + (size_t)bh0 * S_LEN * KBP;
        if (lane == 0) {
            #pragma unroll
            for (int j = 0; j < 2; j++) {
                MBARRIER_EXPECT_TX(wbar + j * 8, WSTAGE);
                bulk_cp(slab + j * WSTAGE,
                        (const char*)Bg0 + ((size_t)j * NSUB + warp * 8) * (KBP * 2),
                        WSTAGE, wbar + j * 8);
            }
        }
        const int mt0 = bid & 63;
        const __half* Ag0 = g_Ah + ((size_t)bh0 * S_LEN + (size_t)mt0 * MROWS) * KC;
        if (tid < 384) {
            int row = tid / 12, c = tid % 12;
            uint4 v = *(const uint4*)((const char*)Ag0 + (size_t)row * (KC * 2) + c * 16);
            *(uint4*)(smraw + SM_A + row * SPADB + c * 16) = v;
        }
        __syncthreads();
    }

    int slot = 0;                                // = global stage L mod 3
    int ph0 = 0, ph1 = 0, ph2 = 0;               // per-slot parity counters

    for (int T = bid; T < NTILES; T += NCTA) {
        const int bh = T >> 6, mt = T & 63;
        const __half* Bg = g_Bh + (size_t)bh * S_LEN * KBP;
        const int T2 = T + NCTA;
        const bool hasNext = (T2 < NTILES);
        const __half* Bg2 = hasNext ? g_Bh + (size_t)(T2 >> 6) * S_LEN * KBP : (const __half*)0;

        // --- A fragments for this tile ---
        uint32_t aLo[6][4], aHi[6][4];
        {
            const uint32_t ab = sA + (lane & 15) * SPADB + ((lane >> 4) << 3) * 2;
            #pragma unroll
            for (int k = 0; k < 6; k++) {
                ldsm_x4(aLo[k], ab + k * 32);
                ldsm_x4(aHi[k], ab + 16 * SPADB + k * 32);
            }
        }

        float s0 = 0.0f, s1 = 0.0f, s2 = 0.0f, s3 = 0.0f;

        #pragma unroll
        for (int s = 0; s < NSUBS; s++) {
            // wait stage L (this slot); flip that slot's parity
            if (slot == 0)      { MBARRIER_WAIT_PARITY(wbar,      ph0); ph0 ^= 1; }
            else if (slot == 1) { MBARRIER_WAIT_PARITY(wbar + 8,  ph1); ph1 ^= 1; }
            else                { MBARRIER_WAIT_PARITY(wbar + 16, ph2); ph2 ^= 1; }

            const uint32_t bb = slab + slot * WSTAGE + bfoff;
            uint32_t b[3][4];
            #pragma unroll
            for (int j = 0; j < 3; j++)
                ldsm_x4(b[j], bb + j * 64);

            // bulk-issue stage L+2 (slot (slot+2)%3): lane 0 only
            {
                const int pfslot = (slot + 2 >= NSTG) ? slot + 2 - NSTG : slot + 2;
                const __half* Bp = (s < NSUBS - 2) ? Bg : Bg2;
                const int sub = (s + 2) & (NSUBS - 1);
                if (Bp && lane == 0) {
                    MBARRIER_EXPECT_TX(wbar + pfslot * 8, WSTAGE);
                    bulk_cp(slab + pfslot * WSTAGE,
                            (const char*)Bp + ((size_t)sub * NSUB + warp * 8) * (KBP * 2),
                            WSTAGE, wbar + pfslot * 8);
                }
            }

            float A0[4] = {0,0,0,0}, A1[4] = {0,0,0,0};
            float C0[4] = {0,0,0,0}, C1[4] = {0,0,0,0};
            #pragma unroll
            for (int j = 0; j < 3; j++) {
                mma_fp16(A0, aLo[2 * j],     &b[j][0]);
                mma_fp16(A1, aLo[2 * j + 1], &b[j][2]);
                mma_fp16(C0, aHi[2 * j],     &b[j][0]);
                mma_fp16(C1, aHi[2 * j + 1], &b[j][2]);
            }

            // exp2 -> fp16 scores to smem; fp32 sums in regs
            float v0 = ex2f(A0[0] + A1[0]), v1 = ex2f(A0[1] + A1[1]);
            float v2 = ex2f(A0[2] + A1[2]), v3 = ex2f(A0[3] + A1[3]);
            float w0 = ex2f(C0[0] + C1[0]), w1 = ex2f(C0[1] + C1[1]);
            float w2 = ex2f(C0[2] + C1[2]), w3 = ex2f(C0[3] + C1[3]);
            s0 += v0 + v1;  s1 += v2 + v3;
            s2 += w0 + w1;  s3 += w2 + w3;

            const uint32_t scs = scbase + s * (NSUB * 2);
            asm volatile("st.shared.b32 [%0], %1;" :: "r"(scs + r0 * SROWB),
                         "r"(h2_to_u32(__floats2half2_rn(v0, v1))) : "memory");
            asm volatile("st.shared.b32 [%0], %1;" :: "r"(scs + (r0 + 8) * SROWB),
                         "r"(h2_to_u32(__floats2half2_rn(v2, v3))) : "memory");
            asm volatile("st.shared.b32 [%0], %1;" :: "r"(scs + (r0 + 16) * SROWB),
                         "r"(h2_to_u32(__floats2half2_rn(w0, w1))) : "memory");
            asm volatile("st.shared.b32 [%0], %1;" :: "r"(scs + (r0 + 24) * SROWB),
                         "r"(h2_to_u32(__floats2half2_rn(w2, w3))) : "memory");

            slot = (slot + 1 >= NSTG) ? 0 : slot + 1;
        }

        // --- deterministic row sums ---
        s0 += __shfl_xor_sync(0xffffffffu, s0, 1);
        s0 += __shfl_xor_sync(0xffffffffu, s0, 2);
        s1 += __shfl_xor_sync(0xffffffffu, s1, 1);
        s1 += __shfl_xor_sync(0xffffffffu, s1, 2);
        s2 += __shfl_xor_sync(0xffffffffu, s2, 1);
        s2 += __shfl_xor_sync(0xffffffffu, s2, 2);
        s3 += __shfl_xor_sync(0xffffffffu, s3, 1);
        s3 += __shfl_xor_sync(0xffffffffu, s3, 2);
        if ((lane & 3) == 0) {
            redp[r0 * 16 + warp] = s0;
            redp[(r0 + 8) * 16 + warp] = s1;
            redp[(r0 + 16) * 16 + warp] = s2;
            redp[(r0 + 24) * 16 + warp] = s3;
        }
        __syncthreads();
        if (tid < MROWS) {
            float t = 0.0f;
            #pragma unroll
            for (int w = 0; w < 16; w++) t += redp[tid * 16 + w];
            rsum[tid] = 1.0f / t;
        }
        __syncthreads();

        // --- prefetch A(next tile) into registers (hides under epilogue) ---
        uint4 av;
        if (hasNext && tid < 384) {
            const __half* Ag2 = g_Ah + ((size_t)(T2 >> 6) * S_LEN + (size_t)(T2 & 63) * MROWS) * KC;
            int row = tid / 12, c = tid % 12;
            av = *(const uint4*)((const char*)Ag2 + (size_t)row * (KC * 2) + c * 16);
        }

        // --- readback + normalize + coalesced DRAM pass ---
        {
            const int row = tid >> 4;            // 0..31
            const int l16 = tid & 15;
            const float inv = rsum[row];
            const uint32_t srow = sSC + row * SROWB;
            float* orow = out + ((size_t)bh * S_LEN + (size_t)mt * MROWS + row) * S_LEN;
            #pragma unroll
            for (int i = 0; i < 16; i++) {
                const int chunk = l16 + i * 16;           // 16B = 8 halves
                uint32_t h[4];
                asm volatile("ld.shared.v4.b32 {%0,%1,%2,%3}, [%4];"
                             : "=r"(h[0]), "=r"(h[1]), "=r"(h[2]), "=r"(h[3])
                             : "r"(srow + chunk * 16));
                float2 f0 = __half22float2(*(__half2*)&h[0]);
                float2 f1 = __half22float2(*(__half2*)&h[1]);
                float2 f2 = __half22float2(*(__half2*)&h[2]);
                float2 f3 = __half22float2(*(__half2*)&h[3]);
                float4 o0 = make_float4(f0.x * inv, f0.y * inv, f1.x * inv, f1.y * inv);
                float4 o1 = make_float4(f2.x * inv, f2.y * inv, f3.x * inv, f3.y * inv);
                *(float4*)(orow + chunk * 8)     = o0;
                *(float4*)(orow + chunk * 8 + 4) = o1;
            }
        }
        __syncthreads();              // sc-smem + rsum reads complete

        if (hasNext && tid < 384) {
            int row = tid / 12, c = tid % 12;
            *(uint4*)(smraw + SM_A + row * SPADB + c * 16) = av;
        }
        __syncthreads();              // A(t+1) visible before next aF ldsm
    }
}

// ---------------------------------------------------------------------------
extern "C" void kernel_launch(void* const* d_in, const int* in_sizes, int n_in,
                              void* d_out, int out_size)
{
    const float* keys      = (const float*)d_in[0];
    const float* queries   = (const float*)d_in[1];
    const float* pos_key   = (const float*)d_in[2];
    const float* pos_query = (const float*)d_in[3];
    float* out = (float*)d_out;

    const size_t prep_total4 = (size_t)BHN * S_LEN * (KC / 4);
    prep_fp16<<<(unsigned)((prep_total4 + 255) / 256), 256>>>(keys, queries, pos_key, pos_query);

    cudaFuncSetAttribute(fused_attn, cudaFuncAttributeMaxDynamicSharedMemorySize, SM_TOT);
    fused_attn<<<NCTA, 512, SM_TOT>>>(out);
}

// round 16
// speedup vs baseline: 1.0622x; 1.0622x over previous
#include <cuda_runtime.h>
#include <cuda_fp16.h>
#include <cstdint>
#include <math.h>

// ---------------- problem constants ----------------
#define S_LEN 2048
#define BHN   64          // B*H
#define DQ    64
#define DP    32
#define KC    96          // concatenated K (q|pq)
#define LOG2E 1.4426950408889634f
#define SCALE_Q (0.125f * LOG2E)               // exp2-folded
#define SCALE_P (0.17677669529663687f * LOG2E) // exp2-folded

#define MROWS 32          // rows per tile (full 2048-wide ownership)
#define NSUB  128         // columns per subtile
#define NSUBS 16          // 2048 / 128
#define NTILES ((S_LEN / MROWS) * BHN)   // 4096
#define NCTA  148         // persistent CTAs (1 per SM)
#define SPADB 208         // A/B smem row stride bytes (13*16B, ldmatrix-clean)
#define NSTG  3           // B ring stages per warp
#define WSTAGE 1664       // per-warp per-stage bytes (8 rows * 208)
#define WSLAB  (NSTG * WSTAGE)        // 4992 B per warp
#define SROWB  4112       // score smem row stride (4096 + 16 skew: conflict-free)

#define SM_A    0                     // A: 32*208 = 6656
#define SM_RED  6656                  // 32*16 partials (2048) + 32 sums (128)
#define SM_SC   8832                  // scores: 32 * 4112 = 131584
#define SM_B    140416                // B slabs: 16 * 4992 = 79872
#define SM_TOT  220288

// fp16 scratch: [bh][s][96]  (clamp+scale(+log2e on A) folded)
__device__ __align__(16) __half g_Ah[(size_t)BHN * S_LEN * KC];
__device__ __align__(16) __half g_Bh[(size_t)BHN * S_LEN * KC];

__device__ __forceinline__ float clamp5(float x) {
    return fminf(fmaxf(x, -5.0f), 5.0f);
}

__device__ __forceinline__ float ex2f(float x) {     // single MUFU.EX2
    float y;
    asm("ex2.approx.f32 %0, %1;" : "=f"(y) : "f"(x));
    return y;
}

__device__ __forceinline__ uint32_t h2_to_u32(__half2 h) {
    union { __half2 h; uint32_t u; } cv;
    cv.h = h;
    return cv.u;
}

__device__ __forceinline__ uint32_t smem_u32(const void* p) {
    uint32_t a;
    asm("{ .reg .u64 t; cvta.to.shared.u64 t, %1; cvt.u32.u64 %0, t; }" : "=r"(a) : "l"(p));
    return a;
}
__device__ __forceinline__ void cp16(uint32_t dst, const void* src) {
    asm volatile("cp.async.cg.shared.global [%0], [%1], 16;" :: "r"(dst), "l"(src));
}
#define CP_COMMIT() asm volatile("cp.async.commit_group;" ::: "memory")
#define CP_WAIT1()  asm volatile("cp.async.wait_group 1;" ::: "memory")

__device__ __forceinline__ void ldsm_x4(uint32_t* r, uint32_t addr) {
    asm volatile("ldmatrix.sync.aligned.m8n8.x4.shared.b16 {%0,%1,%2,%3}, [%4];"
                 : "=r"(r[0]), "=r"(r[1]), "=r"(r[2]), "=r"(r[3]) : "r"(addr));
}
__device__ __forceinline__ void mma_fp16(float* d, const uint32_t* a, const uint32_t* b) {
    asm volatile("mma.sync.aligned.m16n8k16.row.col.f32.f16.f16.f32 "
                 "{%0,%1,%2,%3}, {%4,%5,%6,%7}, {%8,%9}, {%0,%1,%2,%3};"
                 : "+f"(d[0]), "+f"(d[1]), "+f"(d[2]), "+f"(d[3])
                 : "r"(a[0]), "r"(a[1]), "r"(a[2]), "r"(a[3]), "r"(b[0]), "r"(b[1]));
}

// ---------------------------------------------------------------------------
// Pass 0: clamp + scale(+log2e on A) + fp16 convert; float4-vectorized.
// ---------------------------------------------------------------------------
__global__ __launch_bounds__(256) void prep_fp16(
    const float* __restrict__ keys, const float* __restrict__ queries,
    const float* __restrict__ pos_key, const float* __restrict__ pos_query)
{
    size_t idx4 = (size_t)blockIdx.x * blockDim.x + threadIdx.x;
    const size_t total4 = (size_t)BHN * S_LEN * (KC / 4);
    if (idx4 >= total4) return;
    size_t row = idx4 / (KC / 4);
    int c0 = (int)(idx4 % (KC / 4)) * 4;
    float4 va, vb;
    if (c0 < DQ) {
        va = *(const float4*)(queries + row * DQ + c0);
        vb = *(const float4*)(keys + row * DQ + c0);
        va.x = clamp5(va.x) * SCALE_Q; va.y = clamp5(va.y) * SCALE_Q;
        va.z = clamp5(va.z) * SCALE_Q; va.w = clamp5(va.w) * SCALE_Q;
    } else {
        va = *(const float4*)(pos_query + row * DP + (c0 - DQ));
        vb = *(const float4*)(pos_key + row * DP + (c0 - DQ));
        va.x = clamp5(va.x) * SCALE_P; va.y = clamp5(va.y) * SCALE_P;
        va.z = clamp5(va.z) * SCALE_P; va.w = clamp5(va.w) * SCALE_P;
    }
    vb.x = clamp5(vb.x); vb.y = clamp5(vb.y);
    vb.z = clamp5(vb.z); vb.w = clamp5(vb.w);
    *(__half2*)(g_Ah + row * KC + c0)     = __floats2half2_rn(va.x, va.y);
    *(__half2*)(g_Ah + row * KC + c0 + 2) = __floats2half2_rn(va.z, va.w);
    *(__half2*)(g_Bh + row * KC + c0)     = __floats2half2_rn(vb.x, vb.y);
    *(__half2*)(g_Bh + row * KC + c0 + 2) = __floats2half2_rn(vb.z, vb.w);
}

// ---------------------------------------------------------------------------
// Pass 1 (fused, persistent, SOFTWARE-PIPELINED): per tile 32x2048 scores ->
// exp2 (fp16 smem) -> fp32 rowsum -> normalized single-pass write.
// B fragments are pipelined across iterations: the blocking wait_group +
// ldmatrix for stage s+1 sits BETWEEN iter s's MMA issue and its exp/STS
// tail, so stage arrival and ldsm latency overlap in-flight HMMAs, and the
// exp tail overlaps the new ldsm. Ledger unchanged: 2 prologue commits,
// exactly one commit per iter -> wait_group 1 at global stage L guarantees
// stage L landed.
// ---------------------------------------------------------------------------
__global__ __launch_bounds__(512, 1) void fused_attn(float* __restrict__ out)
{
    extern __shared__ __align__(16) char smraw[];
    float* redp = (float*)(smraw + SM_RED);          // [32 rows][16 warps]
    float* rsum = redp + 32 * 16;                    // [32] inverse sums
    const uint32_t sA  = smem_u32(smraw + SM_A);
    const uint32_t sSC = smem_u32(smraw + SM_SC);

    const int tid = threadIdx.x;
    const int lane = tid & 31, warp = tid >> 5;      // 16 warps
    const int bid = blockIdx.x;

    const uint32_t slab = smem_u32(smraw + SM_B) + warp * WSLAB;

    const int r0 = lane >> 2;                       // 0..7
    const int c2 = (lane & 3) * 2;
    const uint32_t bfoff = (lane & 7) * SPADB + (lane >> 3) * 16;
    const uint32_t scbase = sSC + (warp * 8 + c2) * 2;   // + row*SROWB + sub*256

    // per-lane B chunk coords (3 chunks of 16B per lane per stage)
    int br[3], bc[3];
    #pragma unroll
    for (int i = 0; i < 3; i++) {
        int f = lane + i * 32;
        br[i] = f / 12;  bc[i] = f % 12;
    }

    // --- first-tile prologue ---
    {
        const int bh0 = bid >> 6;
        const __half* Bg0 = g_Bh + (size_t)bh0 * S_LEN * KC;
        #pragma unroll
        for (int j = 0; j < 2; j++) {          // B stages 0,1 -> slots 0,1
            #pragma unroll
            for (int i = 0; i < 3; i++)
                cp16(slab + j * WSTAGE + br[i] * SPADB + bc[i] * 16,
                     (const char*)Bg0 + ((size_t)j * NSUB + warp * 8 + br[i]) * (KC * 2) + bc[i] * 16);
            CP_COMMIT();
        }
        const int mt0 = bid & 63;
        const __half* Ag0 = g_Ah + ((size_t)bh0 * S_LEN + (size_t)mt0 * MROWS) * KC;
        if (tid < 384) {
            int row = tid / 12, c = tid % 12;
            uint4 v = *(const uint4*)((const char*)Ag0 + (size_t)row * (KC * 2) + c * 16);
            *(uint4*)(smraw + SM_A + row * SPADB + c * 16) = v;
        }
        __syncthreads();
    }

    int slot = 0;                                // slot of frags currently in b

    for (int T = bid; T < NTILES; T += NCTA) {
        const int bh = T >> 6, mt = T & 63;
        const __half* Bg = g_Bh + (size_t)bh * S_LEN * KC;
        const int T2 = T + NCTA;
        const bool hasNext = (T2 < NTILES);
        const __half* Bg2 = hasNext ? g_Bh + (size_t)(T2 >> 6) * S_LEN * KC : (const __half*)0;

        // --- A fragments for this tile (A smem is sync'd) ---
        uint32_t aLo[6][4], aHi[6][4];
        {
            const uint32_t ab = sA + (lane & 15) * SPADB + ((lane >> 4) << 3) * 2;
            #pragma unroll
            for (int k = 0; k < 6; k++) {
                ldsm_x4(aLo[k], ab + k * 32);
                ldsm_x4(aHi[k], ab + 16 * SPADB + k * 32);
            }
        }

        // --- preload B frags for this tile's subtile 0 ---
        uint32_t b[3][4];
        {
            CP_WAIT1();                 // stage 16*tidx landed
            __syncwarp();
            const uint32_t bb = slab + slot * WSTAGE + bfoff;
            #pragma unroll
            for (int j = 0; j < 3; j++)
                ldsm_x4(b[j], bb + j * 64);
        }

        float s0 = 0.0f, s1 = 0.0f, s2 = 0.0f, s3 = 0.0f;

        #pragma unroll
        for (int s = 0; s < NSUBS; s++) {
            // (1) issue prefetch for stage L+2 (slot (slot+2)%3); commit always
            {
                const int pfslot = (slot + 2 >= NSTG) ? slot + 2 - NSTG : slot + 2;
                const __half* Bp = (s < NSUBS - 2) ? Bg : Bg2;
                const int sub = (s + 2) & (NSUBS - 1);
                if (Bp) {
                    #pragma unroll
                    for (int i = 0; i < 3; i++)
                        cp16(slab + pfslot * WSTAGE + br[i] * SPADB + bc[i] * 16,
                             (const char*)Bp + ((size_t)sub * NSUB + warp * 8 + br[i]) * (KC * 2) + bc[i] * 16);
                }
                CP_COMMIT();
            }

            // (2) MMA with current frags (async issue; results via scoreboard)
            float A0[4] = {0,0,0,0}, A1[4] = {0,0,0,0};
            float C0[4] = {0,0,0,0}, C1[4] = {0,0,0,0};
            #pragma unroll
            for (int j = 0; j < 3; j++) {
                mma_fp16(A0, aLo[2 * j],     &b[j][0]);
                mma_fp16(A1, aLo[2 * j + 1], &b[j][2]);
                mma_fp16(C0, aHi[2 * j],     &b[j][0]);
                mma_fp16(C1, aHi[2 * j + 1], &b[j][2]);
            }

            // (3) wait + load NEXT iter's frags (overlaps in-flight HMMAs)
            if (s < NSUBS - 1) {
                CP_WAIT1();             // stage L+1 landed (commits = 2+L+1)
                __syncwarp();
                slot = (slot + 1 >= NSTG) ? 0 : slot + 1;
                const uint32_t bb = slab + slot * WSTAGE + bfoff;
                #pragma unroll
                for (int j = 0; j < 3; j++)
                    ldsm_x4(b[j], bb + j * 64);
            }

            // (4) exp2 -> fp16 scores to smem; fp32 sums in regs
            float v0 = ex2f(A0[0] + A1[0]), v1 = ex2f(A0[1] + A1[1]);
            float v2 = ex2f(A0[2] + A1[2]), v3 = ex2f(A0[3] + A1[3]);
            float w0 = ex2f(C0[0] + C1[0]), w1 = ex2f(C0[1] + C1[1]);
            float w2 = ex2f(C0[2] + C1[2]), w3 = ex2f(C0[3] + C1[3]);
            s0 += v0 + v1;  s1 += v2 + v3;
            s2 += w0 + w1;  s3 += w2 + w3;

            const uint32_t scs = scbase + s * (NSUB * 2);
            asm volatile("st.shared.b32 [%0], %1;" :: "r"(scs + r0 * SROWB),
                         "r"(h2_to_u32(__floats2half2_rn(v0, v1))) : "memory");
            asm volatile("st.shared.b32 [%0], %1;" :: "r"(scs + (r0 + 8) * SROWB),
                         "r"(h2_to_u32(__floats2half2_rn(v2, v3))) : "memory");
            asm volatile("st.shared.b32 [%0], %1;" :: "r"(scs + (r0 + 16) * SROWB),
                         "r"(h2_to_u32(__floats2half2_rn(w0, w1))) : "memory");
            asm volatile("st.shared.b32 [%0], %1;" :: "r"(scs + (r0 + 24) * SROWB),
                         "r"(h2_to_u32(__floats2half2_rn(w2, w3))) : "memory");
        }
        // advance slot past this tile's last stage for the next tile's preload
        slot = (slot + 1 >= NSTG) ? 0 : slot + 1;

        // --- deterministic row sums ---
        s0 += __shfl_xor_sync(0xffffffffu, s0, 1);
        s0 += __shfl_xor_sync(0xffffffffu, s0, 2);
        s1 += __shfl_xor_sync(0xffffffffu, s1, 1);
        s1 += __shfl_xor_sync(0xffffffffu, s1, 2);
        s2 += __shfl_xor_sync(0xffffffffu, s2, 1);
        s2 += __shfl_xor_sync(0xffffffffu, s2, 2);
        s3 += __shfl_xor_sync(0xffffffffu, s3, 1);
        s3 += __shfl_xor_sync(0xffffffffu, s3, 2);
        if ((lane & 3) == 0) {
            redp[r0 * 16 + warp] = s0;
            redp[(r0 + 8) * 16 + warp] = s1;
            redp[(r0 + 16) * 16 + warp] = s2;
            redp[(r0 + 24) * 16 + warp] = s3;
        }
        __syncthreads();
        if (tid < MROWS) {
            float t = 0.0f;
            #pragma unroll
            for (int w = 0; w < 16; w++) t += redp[tid * 16 + w];
            rsum[tid] = 1.0f / t;
        }
        __syncthreads();

        // --- prefetch A(next tile) into registers (hides under epilogue) ---
        uint4 av;
        if (hasNext && tid < 384) {
            const __half* Ag2 = g_Ah + ((size_t)(T2 >> 6) * S_LEN + (size_t)(T2 & 63) * MROWS) * KC;
            int row = tid / 12, c = tid % 12;
            av = *(const uint4*)((const char*)Ag2 + (size_t)row * (KC * 2) + c * 16);
        }

        // --- readback + normalize + coalesced DRAM pass ---
        {
            const int row = tid >> 4;            // 0..31
            const int l16 = tid & 15;
            const float inv = rsum[row];
            const uint32_t srow = sSC + row * SROWB;
            float* orow = out + ((size_t)bh * S_LEN + (size_t)mt * MROWS + row) * S_LEN;
            #pragma unroll
            for (int i = 0; i < 16; i++) {
                const int chunk = l16 + i * 16;           // 16B = 8 halves
                uint32_t h[4];
                asm volatile("ld.shared.v4.b32 {%0,%1,%2,%3}, [%4];"
                             : "=r"(h[0]), "=r"(h[1]), "=r"(h[2]), "=r"(h[3])
                             : "r"(srow + chunk * 16));
                float2 f0 = __half22float2(*(__half2*)&h[0]);
                float2 f1 = __half22float2(*(__half2*)&h[1]);
                float2 f2 = __half22float2(*(__half2*)&h[2]);
                float2 f3 = __half22float2(*(__half2*)&h[3]);
                float4 o0 = make_float4(f0.x * inv, f0.y * inv, f1.x * inv, f1.y * inv);
                float4 o1 = make_float4(f2.x * inv, f2.y * inv, f3.x * inv, f3.y * inv);
                *(float4*)(orow + chunk * 8)     = o0;
                *(float4*)(orow + chunk * 8 + 4) = o1;
            }
        }
        __syncthreads();              // all reads of sc-smem + rsum complete

        if (hasNext && tid < 384) {
            int row = tid / 12, c = tid % 12;
            *(uint4*)(smraw + SM_A + row * SPADB + c * 16) = av;
        }
        __syncthreads();              // A(t+1) visible before next aF ldsm
    }
}

// ---------------------------------------------------------------------------
extern "C" void kernel_launch(void* const* d_in, const int* in_sizes, int n_in,
                              void* d_out, int out_size)
{
    const float* keys      = (const float*)d_in[0];
    const float* queries   = (const float*)d_in[1];
    const float* pos_key   = (const float*)d_in[2];
    const float* pos_query = (const float*)d_in[3];
    float* out = (float*)d_out;

    const size_t prep_total4 = (size_t)BHN * S_LEN * (KC / 4);
    prep_fp16<<<(unsigned)((prep_total4 + 255) / 256), 256>>>(keys, queries, pos_key, pos_query);

    cudaFuncSetAttribute(fused_attn, cudaFuncAttributeMaxDynamicSharedMemorySize, SM_TOT);
    fused_attn<<<NCTA, 512, SM_TOT>>>(out);
}